// round 7
// baseline (speedup 1.0000x reference)
#include <cuda_runtime.h>
#include <cuda_bf16.h>
#include <cstdint>

// Problem constants
#define NPTS   1048576
#define CIN    64
#define COUT   96
#define NB     4
#define NSEG2  1048576   // 4 * 64^3
#define NSEG4  131072    // 4 * 32^3
#define NSEG8  16384     // 4 * 16^3

// ---------------- static device scratch ----------------
__device__ float g_sums2[(long)NSEG2 * 64];   // 268 MB
__device__ float g_cnt2[NSEG2];
__device__ float g_sums4[(long)NSEG4 * 64];   // 33.5 MB
__device__ float g_cnt4[NSEG4];
__device__ float g_sums8[(long)NSEG8 * 64];   // 4 MB
__device__ float g_cnt8[NSEG8];
__device__ float g_base0[NB * COUT];
__device__ float g_Z8[(long)NSEG8 * COUT];    // 6.3 MB
__device__ float g_Z4[(long)NSEG4 * COUT];    // 50 MB
__device__ int   g_seg2[NPTS];
// pre-split W blocks (levels 2,4,8), packed bf16x2: [L][o][j] j = k/2
__device__ uint32_t g_Wh32[3 * 96 * 32];
__device__ uint32_t g_Wl32[3 * 96 * 32];

// ---------------- PTX helpers ----------------
__device__ __forceinline__ void red_add_v4(float* addr, float4 v) {
    asm volatile("red.global.add.v4.f32 [%0], {%1, %2, %3, %4};"
                 :: "l"(addr), "f"(v.x), "f"(v.y), "f"(v.z), "f"(v.w)
                 : "memory");
}

__device__ __forceinline__ void hmma16816(
    float& c0, float& c1, float& c2, float& c3,
    uint32_t a0, uint32_t a1, uint32_t a2, uint32_t a3,
    uint32_t b0, uint32_t b1)
{
    asm volatile(
        "mma.sync.aligned.m16n8k16.row.col.f32.bf16.bf16.f32 "
        "{%0,%1,%2,%3}, {%4,%5,%6,%7}, {%8,%9}, {%0,%1,%2,%3};"
        : "+f"(c0), "+f"(c1), "+f"(c2), "+f"(c3)
        : "r"(a0), "r"(a1), "r"(a2), "r"(a3), "r"(b0), "r"(b1));
}

// split float pair into (hi bf16x2, lo bf16x2)
__device__ __forceinline__ void split2(float x, float y, uint32_t& hi, uint32_t& lo) {
    __nv_bfloat16 hx = __float2bfloat16_rn(x);
    __nv_bfloat16 hy = __float2bfloat16_rn(y);
    __nv_bfloat16 lx = __float2bfloat16_rn(x - __bfloat162float(hx));
    __nv_bfloat16 ly = __float2bfloat16_rn(y - __bfloat162float(hy));
    __nv_bfloat162 h = {hx, hy};
    __nv_bfloat162 l = {lx, ly};
    hi = *(uint32_t*)&h;
    lo = *(uint32_t*)&l;
}

// ---------------- kernel 0: pre-split W into bf16 hi/lo tables ----------------
__global__ __launch_bounds__(256) void split_w_kernel(const float* __restrict__ W) {
    int idx = blockIdx.x * 256 + threadIdx.x;   // 3*96*32 = 9216
    if (idx >= 9216) return;
    int L = idx / 3072;
    int r = idx - L * 3072;
    int o = r >> 5, j = r & 31;
    const float* src = W + o * 256 + 64 + L * 64 + 2 * j;
    uint32_t h, l;
    split2(src[0], src[1], h, l);
    g_Wh32[idx] = h;
    g_Wl32[idx] = l;
}

// ---------------- kernel 1: zero level-2 scratch only ----------------
__global__ void zero_kernel() {
    long tid = (long)blockIdx.x * blockDim.x + threadIdx.x;
    long stride = (long)gridDim.x * blockDim.x;
    float4 z = make_float4(0.f, 0.f, 0.f, 0.f);
    float4* s2 = (float4*)g_sums2;
    for (long i = tid; i < (long)NSEG2 * 16; i += stride) s2[i] = z;
    float4* c2 = (float4*)g_cnt2;
    for (long i = tid; i < NSEG2 / 4; i += stride) c2[i] = z;
}

// ---------------- kernel 2: scatter into level-2 ONLY ----------------
__global__ __launch_bounds__(256) void scatter_kernel(
    const float4* __restrict__ feats4,
    const int* __restrict__ coords,
    const int* __restrict__ batch)
{
    int p = blockIdx.x * 256 + threadIdx.x;
    if (p >= NPTS) return;
    int x = coords[3 * p + 0];
    int y = coords[3 * p + 1];
    int z = coords[3 * p + 2];
    int b = batch[p];

    int s2 = (b << 18) | ((x >> 1) << 12) | ((y >> 1) << 6) | (z >> 1);
    g_seg2[p] = s2;
    atomicAdd(&g_cnt2[s2], 1.0f);

    float* p2 = &g_sums2[(long)s2 * 64];
    const float4* f = feats4 + (long)p * 16;
#pragma unroll
    for (int i = 0; i < 16; i++) {
        red_add_v4(p2 + 4 * i, f[i]);
    }
}

// ---------------- kernel 2b: hierarchical reductions ----------------
__global__ __launch_bounds__(256) void reduce4_kernel() {
    int t = blockIdx.x * 256 + threadIdx.x;   // NSEG4 * 16 tasks
    int kc = t & 15;
    int s4 = t >> 4;
    int b = s4 >> 15, x = (s4 >> 10) & 31, y = (s4 >> 5) & 31, z = s4 & 31;
    int base = (b << 18) | ((x << 1) << 12) | ((y << 1) << 6) | (z << 1);
    float4 acc = make_float4(0.f, 0.f, 0.f, 0.f);
#pragma unroll
    for (int d = 0; d < 8; d++) {
        int s2 = base + (((d >> 2) & 1) << 12) + (((d >> 1) & 1) << 6) + (d & 1);
        float4 v = *(const float4*)&g_sums2[(long)s2 * 64 + kc * 4];
        acc.x += v.x; acc.y += v.y; acc.z += v.z; acc.w += v.w;
    }
    *(float4*)&g_sums4[(long)s4 * 64 + kc * 4] = acc;
    if (kc == 0) {
        float c = 0.f;
#pragma unroll
        for (int d = 0; d < 8; d++)
            c += g_cnt2[base + (((d >> 2) & 1) << 12) + (((d >> 1) & 1) << 6) + (d & 1)];
        g_cnt4[s4] = c;
    }
}

__global__ __launch_bounds__(256) void reduce8_kernel() {
    int t = blockIdx.x * 256 + threadIdx.x;   // NSEG8 * 16 tasks
    int kc = t & 15;
    int s8 = t >> 4;
    int b = s8 >> 12, x = (s8 >> 8) & 15, y = (s8 >> 4) & 15, z = s8 & 15;
    int base = (b << 15) | ((x << 1) << 10) | ((y << 1) << 5) | (z << 1);
    float4 acc = make_float4(0.f, 0.f, 0.f, 0.f);
#pragma unroll
    for (int d = 0; d < 8; d++) {
        int s4 = base + (((d >> 2) & 1) << 10) + (((d >> 1) & 1) << 5) + (d & 1);
        float4 v = *(const float4*)&g_sums4[(long)s4 * 64 + kc * 4];
        acc.x += v.x; acc.y += v.y; acc.z += v.z; acc.w += v.w;
    }
    *(float4*)&g_sums8[(long)s8 * 64 + kc * 4] = acc;
    if (kc == 0) {
        float c = 0.f;
#pragma unroll
        for (int d = 0; d < 8; d++)
            c += g_cnt4[base + (((d >> 2) & 1) << 10) + (((d >> 1) & 1) << 5) + (d & 1)];
        g_cnt8[s8] = c;
    }
}

// ---------------- kernel 3: level-0 reduce + base projection ----------------
__global__ __launch_bounds__(256) void l0_kernel(
    const float* __restrict__ W, const float* __restrict__ bias)
{
    int b = blockIdx.x;
    int tid = threadIdx.x;
    __shared__ float sm[4][64];
    __shared__ float smean[64];
    __shared__ float scnt[256];

    int c = tid & 63, g = tid >> 6;
    const float* base = g_sums8 + (long)b * 4096 * 64;
    float acc = 0.f;
    for (int s = g; s < 4096; s += 4) acc += base[s * 64 + c];
    sm[g][c] = acc;

    float ca = 0.f;
    for (int s = tid; s < 4096; s += 256) ca += g_cnt8[b * 4096 + s];
    scnt[tid] = ca;
    __syncthreads();

    for (int off = 128; off > 0; off >>= 1) {
        if (tid < off) scnt[tid] += scnt[tid + off];
        __syncthreads();
    }
    if (tid < 64) {
        smean[tid] = (sm[0][tid] + sm[1][tid] + sm[2][tid] + sm[3][tid])
                   / fmaxf(scnt[0], 1.0f);
    }
    __syncthreads();
    if (tid < 96) {
        float a = bias[tid];
        const float* wr = W + tid * 256;  // global block = cols [0,64)
#pragma unroll 8
        for (int k = 0; k < 64; k++) a += wr[k] * smean[k];
        g_base0[b * COUT + tid] = a;
    }
}

// ---------------- HMMA transform for levels 8 and 4 (bf16x3) ----------------
// 64 segs x 96 outs per block; Z_lvl = Z_parent + W_lvl @ mean_lvl.
#define A_STRIDE 72   // halves per row, padded

template <int LEVEL>
__global__ __launch_bounds__(128) void transform_hmma_kernel()
{
    __shared__ __align__(16) __nv_bfloat16 sh_Ah[64 * A_STRIDE];
    __shared__ __align__(16) __nv_bfloat16 sh_Al[64 * A_STRIDE];

    int tid  = threadIdx.x;
    int wid  = tid >> 5;
    int lane = tid & 31;
    int base = blockIdx.x * 64;

    const float* SUMS = (LEVEL == 4) ? g_sums4 : g_sums8;
    const float* CNT  = (LEVEL == 4) ? g_cnt4  : g_cnt8;
    const int LIDX = (LEVEL == 4) ? 1 : 2;

    // stage A: 64 mean rows -> bf16 hi/lo. 64 rows x 16 chunks of 4 floats
    for (int it = tid; it < 1024; it += 128) {
        int slot = it >> 4, kc = it & 15;
        int s = base + slot;
        float inv = 1.0f / fmaxf(CNT[s], 1.0f);
        float4 v = *(const float4*)&SUMS[(long)s * 64 + kc * 4];
        uint32_t h0, l0, h1, l1;
        split2(v.x * inv, v.y * inv, h0, l0);
        split2(v.z * inv, v.w * inv, h1, l1);
        uint32_t* dh = (uint32_t*)&sh_Ah[slot * A_STRIDE + kc * 4];
        uint32_t* dl = (uint32_t*)&sh_Al[slot * A_STRIDE + kc * 4];
        dh[0] = h0; dh[1] = h1;
        dl[0] = l0; dl[1] = l1;
    }
    __syncthreads();

    int warp_m = wid * 16;
    int grp = lane >> 2;
    int qid = lane & 3;

    const uint32_t* Wh = g_Wh32 + LIDX * 3072;
    const uint32_t* Wl = g_Wl32 + LIDX * 3072;

    float acc[12][4];
#pragma unroll
    for (int t = 0; t < 12; t++)
#pragma unroll
        for (int j = 0; j < 4; j++) acc[t][j] = 0.f;

#pragma unroll
    for (int ks = 0; ks < 4; ks++) {
        int k0 = ks * 16 + qid * 2;
        int ra = (warp_m + grp) * A_STRIDE;
        int rb = (warp_m + grp + 8) * A_STRIDE;
        uint32_t ah0 = *(const uint32_t*)&sh_Ah[ra + k0];
        uint32_t ah1 = *(const uint32_t*)&sh_Ah[rb + k0];
        uint32_t ah2 = *(const uint32_t*)&sh_Ah[ra + k0 + 8];
        uint32_t ah3 = *(const uint32_t*)&sh_Ah[rb + k0 + 8];
        uint32_t al0 = *(const uint32_t*)&sh_Al[ra + k0];
        uint32_t al1 = *(const uint32_t*)&sh_Al[rb + k0];
        uint32_t al2 = *(const uint32_t*)&sh_Al[ra + k0 + 8];
        uint32_t al3 = *(const uint32_t*)&sh_Al[rb + k0 + 8];
        int wb = ks * 8 + qid;
#pragma unroll
        for (int t = 0; t < 12; t++) {
            int n = t * 8 + grp;
            uint32_t bh0 = Wh[n * 32 + wb];
            uint32_t bh1 = Wh[n * 32 + wb + 4];
            uint32_t bl0 = Wl[n * 32 + wb];
            uint32_t bl1 = Wl[n * 32 + wb + 4];
            hmma16816(acc[t][0], acc[t][1], acc[t][2], acc[t][3],
                      ah0, ah1, ah2, ah3, bh0, bh1);
            hmma16816(acc[t][0], acc[t][1], acc[t][2], acc[t][3],
                      ah0, ah1, ah2, ah3, bl0, bl1);
            hmma16816(acc[t][0], acc[t][1], acc[t][2], acc[t][3],
                      al0, al1, al2, al3, bh0, bh1);
        }
    }

    // epilogue
    int slot0 = warp_m + grp;
    int slot1 = slot0 + 8;
    int s0 = base + slot0;
    int s1 = base + slot1;

    const float* p0;
    const float* p1;
    float* zout;
    if (LEVEL == 8) {
        p0 = &g_base0[(s0 >> 12) * COUT];
        p1 = &g_base0[(s1 >> 12) * COUT];
        zout = g_Z8;
    } else {
        int bb0 = s0 >> 15, xx0 = (s0 >> 10) & 31, yy0 = (s0 >> 5) & 31, zz0 = s0 & 31;
        int bb1 = s1 >> 15, xx1 = (s1 >> 10) & 31, yy1 = (s1 >> 5) & 31, zz1 = s1 & 31;
        p0 = &g_Z8[(long)((bb0 << 12) | ((xx0 >> 1) << 8) | ((yy0 >> 1) << 4) | (zz0 >> 1)) * COUT];
        p1 = &g_Z8[(long)((bb1 << 12) | ((xx1 >> 1) << 8) | ((yy1 >> 1) << 4) | (zz1 >> 1)) * COUT];
        zout = g_Z4;
    }
    float* d0 = zout + (long)s0 * COUT;
    float* d1 = zout + (long)s1 * COUT;

#pragma unroll
    for (int t = 0; t < 12; t++) {
        int c = t * 8 + qid * 2;
        float2 za = *(const float2*)&p0[c];
        float2 zb = *(const float2*)&p1[c];
        *(float2*)&d0[c] = make_float2(acc[t][0] + za.x, acc[t][1] + za.y);
        *(float2*)&d1[c] = make_float2(acc[t][2] + zb.x, acc[t][3] + zb.y);
    }
}

// ---------------- fused level-2 transform + output (bf16x3 HMMA) ----------------
__global__ __launch_bounds__(128) void fused_mma_kernel(float* __restrict__ out)
{
    __shared__ __align__(16) __nv_bfloat16 sh_Ah[64 * A_STRIDE];
    __shared__ __align__(16) __nv_bfloat16 sh_Al[64 * A_STRIDE];
    __shared__ int   s_s4[64];
    __shared__ int   s_sid[64];
    __shared__ float s_inv[64];

    int tid  = threadIdx.x;
    int wid  = tid >> 5;
    int lane = tid & 31;
    int pbase = blockIdx.x * 64;

    if (tid < 64) {
        int s2 = g_seg2[pbase + tid];
        s_sid[tid] = s2;
        int bb = s2 >> 18, xx = (s2 >> 12) & 63, yy = (s2 >> 6) & 63, zz = s2 & 63;
        s_s4[tid] = (bb << 15) | ((xx >> 1) << 10) | ((yy >> 1) << 5) | (zz >> 1);
        s_inv[tid] = 1.0f / fmaxf(g_cnt2[s2], 1.0f);
    }
    __syncthreads();

    // stage A: 64 mean rows -> bf16 hi/lo
    for (int it = tid; it < 1024; it += 128) {
        int slot = it >> 4, kc = it & 15;
        int s = s_sid[slot];
        float inv = s_inv[slot];
        float4 v = *(const float4*)&g_sums2[(long)s * 64 + kc * 4];
        uint32_t h0, l0, h1, l1;
        split2(v.x * inv, v.y * inv, h0, l0);
        split2(v.z * inv, v.w * inv, h1, l1);
        uint32_t* dh = (uint32_t*)&sh_Ah[slot * A_STRIDE + kc * 4];
        uint32_t* dl = (uint32_t*)&sh_Al[slot * A_STRIDE + kc * 4];
        dh[0] = h0; dh[1] = h1;
        dl[0] = l0; dl[1] = l1;
    }
    __syncthreads();

    int warp_m = wid * 16;
    int grp = lane >> 2;
    int qid = lane & 3;

    const uint32_t* Wh = g_Wh32;       // level-2 block (LIDX 0)
    const uint32_t* Wl = g_Wl32;

    float acc[12][4];
#pragma unroll
    for (int t = 0; t < 12; t++)
#pragma unroll
        for (int j = 0; j < 4; j++) acc[t][j] = 0.f;

#pragma unroll
    for (int ks = 0; ks < 4; ks++) {
        int k0 = ks * 16 + qid * 2;
        int ra = (warp_m + grp) * A_STRIDE;
        int rb = (warp_m + grp + 8) * A_STRIDE;
        uint32_t ah0 = *(const uint32_t*)&sh_Ah[ra + k0];
        uint32_t ah1 = *(const uint32_t*)&sh_Ah[rb + k0];
        uint32_t ah2 = *(const uint32_t*)&sh_Ah[ra + k0 + 8];
        uint32_t ah3 = *(const uint32_t*)&sh_Ah[rb + k0 + 8];
        uint32_t al0 = *(const uint32_t*)&sh_Al[ra + k0];
        uint32_t al1 = *(const uint32_t*)&sh_Al[rb + k0];
        uint32_t al2 = *(const uint32_t*)&sh_Al[ra + k0 + 8];
        uint32_t al3 = *(const uint32_t*)&sh_Al[rb + k0 + 8];
        int wb = ks * 8 + qid;
#pragma unroll
        for (int t = 0; t < 12; t++) {
            int n = t * 8 + grp;
            uint32_t bh0 = Wh[n * 32 + wb];
            uint32_t bh1 = Wh[n * 32 + wb + 4];
            uint32_t bl0 = Wl[n * 32 + wb];
            uint32_t bl1 = Wl[n * 32 + wb + 4];
            hmma16816(acc[t][0], acc[t][1], acc[t][2], acc[t][3],
                      ah0, ah1, ah2, ah3, bh0, bh1);
            hmma16816(acc[t][0], acc[t][1], acc[t][2], acc[t][3],
                      ah0, ah1, ah2, ah3, bl0, bl1);
            hmma16816(acc[t][0], acc[t][1], acc[t][2], acc[t][3],
                      al0, al1, al2, al3, bh0, bh1);
        }
    }

    // epilogue: out[p] = Z4[s4(p)] + D[p]
    int slot0 = warp_m + grp;
    int slot1 = slot0 + 8;
    const float* z0 = &g_Z4[(long)s_s4[slot0] * COUT];
    const float* z1 = &g_Z4[(long)s_s4[slot1] * COUT];
    float* d0 = out + (long)(pbase + slot0) * COUT;
    float* d1 = out + (long)(pbase + slot1) * COUT;

#pragma unroll
    for (int t = 0; t < 12; t++) {
        int c = t * 8 + qid * 2;
        float2 za = *(const float2*)&z0[c];
        float2 zb = *(const float2*)&z1[c];
        *(float2*)&d0[c] = make_float2(acc[t][0] + za.x, acc[t][1] + za.y);
        *(float2*)&d1[c] = make_float2(acc[t][2] + zb.x, acc[t][3] + zb.y);
    }
}

// ---------------- launcher ----------------
extern "C" void kernel_launch(void* const* d_in, const int* in_sizes, int n_in,
                              void* d_out, int out_size)
{
    const float* feats  = (const float*)d_in[0];
    const int*   coords = (const int*)d_in[1];
    const int*   batch  = (const int*)d_in[2];
    const float* W      = (const float*)d_in[3];
    const float* bias   = (const float*)d_in[4];

    zero_kernel<<<2048, 256>>>();
    split_w_kernel<<<36, 256>>>(W);
    scatter_kernel<<<NPTS / 256, 256>>>((const float4*)feats, coords, batch);
    reduce4_kernel<<<(NSEG4 * 16) / 256, 256>>>();
    reduce8_kernel<<<(NSEG8 * 16) / 256, 256>>>();
    l0_kernel<<<NB, 256>>>(W, bias);
    transform_hmma_kernel<8><<<NSEG8 / 64, 128>>>();
    transform_hmma_kernel<4><<<NSEG4 / 64, 128>>>();
    fused_mma_kernel<<<NPTS / 64, 128>>>((float*)d_out);
}

// round 8
// speedup vs baseline: 1.2642x; 1.2642x over previous
#include <cuda_runtime.h>
#include <cuda_bf16.h>
#include <cstdint>

// Problem constants
#define NPTS   1048576
#define CIN    64
#define COUT   96
#define NB     4
#define NSEG2  1048576   // 4 * 64^3
#define NSEG4  131072    // 4 * 32^3
#define NSEG8  16384     // 4 * 16^3

// ---------------- static device scratch ----------------
__device__ float g_sums2[(long)NSEG2 * 64];   // 268 MB
__device__ float g_cnt2[NSEG2];
__device__ float g_sums4[(long)NSEG4 * 64];   // 33.5 MB
__device__ float g_cnt4[NSEG4];
__device__ float g_sums8[(long)NSEG8 * 64];   // 4 MB
__device__ float g_cnt8[NSEG8];
__device__ float g_base0[NB * COUT];
__device__ float g_Z8[(long)NSEG8 * COUT];    // 6.3 MB
__device__ float g_Z4[(long)NSEG4 * COUT];    // 50 MB
__device__ int   g_seg2[NPTS];
// pre-split W blocks (levels 2,4,8), packed bf16x2: [L][o][j], j = k/2
__device__ uint32_t g_Wh32[3 * 96 * 32];
__device__ uint32_t g_Wl32[3 * 96 * 32];

// ---------------- PTX helpers ----------------
__device__ __forceinline__ void red_add_v4(float* addr, float4 v) {
    asm volatile("red.global.add.v4.f32 [%0], {%1, %2, %3, %4};"
                 :: "l"(addr), "f"(v.x), "f"(v.y), "f"(v.z), "f"(v.w)
                 : "memory");
}

__device__ __forceinline__ void hmma16816(
    float& c0, float& c1, float& c2, float& c3,
    uint32_t a0, uint32_t a1, uint32_t a2, uint32_t a3,
    uint32_t b0, uint32_t b1)
{
    asm volatile(
        "mma.sync.aligned.m16n8k16.row.col.f32.bf16.bf16.f32 "
        "{%0,%1,%2,%3}, {%4,%5,%6,%7}, {%8,%9}, {%0,%1,%2,%3};"
        : "+f"(c0), "+f"(c1), "+f"(c2), "+f"(c3)
        : "r"(a0), "r"(a1), "r"(a2), "r"(a3), "r"(b0), "r"(b1));
}

// split float pair into (hi bf16x2, lo bf16x2)
__device__ __forceinline__ void split2(float x, float y, uint32_t& hi, uint32_t& lo) {
    __nv_bfloat16 hx = __float2bfloat16_rn(x);
    __nv_bfloat16 hy = __float2bfloat16_rn(y);
    __nv_bfloat16 lx = __float2bfloat16_rn(x - __bfloat162float(hx));
    __nv_bfloat16 ly = __float2bfloat16_rn(y - __bfloat162float(hy));
    __nv_bfloat162 h = {hx, hy};
    __nv_bfloat162 l = {lx, ly};
    hi = *(uint32_t*)&h;
    lo = *(uint32_t*)&l;
}

// ---------------- kernel 0: pre-split W into bf16 hi/lo tables ----------------
__global__ __launch_bounds__(256) void split_w_kernel(const float* __restrict__ W) {
    int idx = blockIdx.x * 256 + threadIdx.x;   // 3*96*32 = 9216
    if (idx >= 9216) return;
    int L = idx / 3072;
    int r = idx - L * 3072;
    int o = r >> 5, j = r & 31;
    const float* src = W + o * 256 + 64 + L * 64 + 2 * j;
    uint32_t h, l;
    split2(src[0], src[1], h, l);
    g_Wh32[idx] = h;
    g_Wl32[idx] = l;
}

// ---------------- kernel 1: zero level-2 scratch only ----------------
__global__ void zero_kernel() {
    long tid = (long)blockIdx.x * blockDim.x + threadIdx.x;
    long stride = (long)gridDim.x * blockDim.x;
    float4 z = make_float4(0.f, 0.f, 0.f, 0.f);
    float4* s2 = (float4*)g_sums2;
    for (long i = tid; i < (long)NSEG2 * 16; i += stride) s2[i] = z;
    float4* c2 = (float4*)g_cnt2;
    for (long i = tid; i < NSEG2 / 4; i += stride) c2[i] = z;
}

// ---------------- kernel 2: scatter into level-2 ONLY ----------------
__global__ __launch_bounds__(256) void scatter_kernel(
    const float4* __restrict__ feats4,
    const int* __restrict__ coords,
    const int* __restrict__ batch)
{
    int p = blockIdx.x * 256 + threadIdx.x;
    if (p >= NPTS) return;
    int x = coords[3 * p + 0];
    int y = coords[3 * p + 1];
    int z = coords[3 * p + 2];
    int b = batch[p];

    int s2 = (b << 18) | ((x >> 1) << 12) | ((y >> 1) << 6) | (z >> 1);
    g_seg2[p] = s2;
    atomicAdd(&g_cnt2[s2], 1.0f);

    float* p2 = &g_sums2[(long)s2 * 64];
    const float4* f = feats4 + (long)p * 16;
#pragma unroll
    for (int i = 0; i < 16; i++) {
        red_add_v4(p2 + 4 * i, f[i]);
    }
}

// ---------------- kernel 2b: hierarchical reductions ----------------
__global__ __launch_bounds__(256) void reduce4_kernel() {
    int t = blockIdx.x * 256 + threadIdx.x;   // NSEG4 * 16 tasks
    int kc = t & 15;
    int s4 = t >> 4;
    int b = s4 >> 15, x = (s4 >> 10) & 31, y = (s4 >> 5) & 31, z = s4 & 31;
    int base = (b << 18) | ((x << 1) << 12) | ((y << 1) << 6) | (z << 1);
    float4 acc = make_float4(0.f, 0.f, 0.f, 0.f);
#pragma unroll
    for (int d = 0; d < 8; d++) {
        int s2 = base + (((d >> 2) & 1) << 12) + (((d >> 1) & 1) << 6) + (d & 1);
        float4 v = *(const float4*)&g_sums2[(long)s2 * 64 + kc * 4];
        acc.x += v.x; acc.y += v.y; acc.z += v.z; acc.w += v.w;
    }
    *(float4*)&g_sums4[(long)s4 * 64 + kc * 4] = acc;
    if (kc == 0) {
        float c = 0.f;
#pragma unroll
        for (int d = 0; d < 8; d++)
            c += g_cnt2[base + (((d >> 2) & 1) << 12) + (((d >> 1) & 1) << 6) + (d & 1)];
        g_cnt4[s4] = c;
    }
}

__global__ __launch_bounds__(256) void reduce8_kernel() {
    int t = blockIdx.x * 256 + threadIdx.x;   // NSEG8 * 16 tasks
    int kc = t & 15;
    int s8 = t >> 4;
    int b = s8 >> 12, x = (s8 >> 8) & 15, y = (s8 >> 4) & 15, z = s8 & 15;
    int base = (b << 15) | ((x << 1) << 10) | ((y << 1) << 5) | (z << 1);
    float4 acc = make_float4(0.f, 0.f, 0.f, 0.f);
#pragma unroll
    for (int d = 0; d < 8; d++) {
        int s4 = base + (((d >> 2) & 1) << 10) + (((d >> 1) & 1) << 5) + (d & 1);
        float4 v = *(const float4*)&g_sums4[(long)s4 * 64 + kc * 4];
        acc.x += v.x; acc.y += v.y; acc.z += v.z; acc.w += v.w;
    }
    *(float4*)&g_sums8[(long)s8 * 64 + kc * 4] = acc;
    if (kc == 0) {
        float c = 0.f;
#pragma unroll
        for (int d = 0; d < 8; d++)
            c += g_cnt4[base + (((d >> 2) & 1) << 10) + (((d >> 1) & 1) << 5) + (d & 1)];
        g_cnt8[s8] = c;
    }
}

// ---------------- kernel 3: level-0 reduce + base projection ----------------
__global__ __launch_bounds__(256) void l0_kernel(
    const float* __restrict__ W, const float* __restrict__ bias)
{
    int b = blockIdx.x;
    int tid = threadIdx.x;
    __shared__ float sm[4][64];
    __shared__ float smean[64];
    __shared__ float scnt[256];

    int c = tid & 63, g = tid >> 6;
    const float* base = g_sums8 + (long)b * 4096 * 64;
    float acc = 0.f;
    for (int s = g; s < 4096; s += 4) acc += base[s * 64 + c];
    sm[g][c] = acc;

    float ca = 0.f;
    for (int s = tid; s < 4096; s += 256) ca += g_cnt8[b * 4096 + s];
    scnt[tid] = ca;
    __syncthreads();

    for (int off = 128; off > 0; off >>= 1) {
        if (tid < off) scnt[tid] += scnt[tid + off];
        __syncthreads();
    }
    if (tid < 64) {
        smean[tid] = (sm[0][tid] + sm[1][tid] + sm[2][tid] + sm[3][tid])
                   / fmaxf(scnt[0], 1.0f);
    }
    __syncthreads();
    if (tid < 96) {
        float a = bias[tid];
        const float* wr = W + tid * 256;  // global block = cols [0,64)
#pragma unroll 8
        for (int k = 0; k < 64; k++) a += wr[k] * smean[k];
        g_base0[b * COUT + tid] = a;
    }
}

// ---------------- shared HMMA tile machinery ----------------
#define A_STRIDE 72   // halves per A row, padded
#define B_U32    36   // uint32 per B row (64 halves padded to 72 -> 36 u32)

// stage pre-split W level block into smem (conflict-free layout)
__device__ __forceinline__ void stage_W(uint32_t* shBh, uint32_t* shBl,
                                        const uint32_t* __restrict__ Wh,
                                        const uint32_t* __restrict__ Wl,
                                        int tid)
{
    for (int idx = tid; idx < 3072; idx += 128) {
        int o = idx >> 5, j = idx & 31;
        shBh[o * B_U32 + j] = Wh[idx];
        shBl[o * B_U32 + j] = Wl[idx];
    }
}

// core bf16x3 MMA over staged A (64 rows) and W (96 rows), per-warp m16 x n96
__device__ __forceinline__ void mma_tile(
    const __nv_bfloat16* shAh, const __nv_bfloat16* shAl,
    const uint32_t* shBh, const uint32_t* shBl,
    int warp_m, int grp, int qid, float acc[12][4])
{
#pragma unroll
    for (int ks = 0; ks < 4; ks++) {
        int k0 = ks * 16 + qid * 2;
        int ra = (warp_m + grp) * A_STRIDE;
        int rb = (warp_m + grp + 8) * A_STRIDE;
        uint32_t ah0 = *(const uint32_t*)&shAh[ra + k0];
        uint32_t ah1 = *(const uint32_t*)&shAh[rb + k0];
        uint32_t ah2 = *(const uint32_t*)&shAh[ra + k0 + 8];
        uint32_t ah3 = *(const uint32_t*)&shAh[rb + k0 + 8];
        uint32_t al0 = *(const uint32_t*)&shAl[ra + k0];
        uint32_t al1 = *(const uint32_t*)&shAl[rb + k0];
        uint32_t al2 = *(const uint32_t*)&shAl[ra + k0 + 8];
        uint32_t al3 = *(const uint32_t*)&shAl[rb + k0 + 8];
        int wb = ks * 8 + qid;
#pragma unroll
        for (int t = 0; t < 12; t++) {
            int n = t * 8 + grp;
            uint32_t bh0 = shBh[n * B_U32 + wb];
            uint32_t bh1 = shBh[n * B_U32 + wb + 4];
            uint32_t bl0 = shBl[n * B_U32 + wb];
            uint32_t bl1 = shBl[n * B_U32 + wb + 4];
            hmma16816(acc[t][0], acc[t][1], acc[t][2], acc[t][3],
                      ah0, ah1, ah2, ah3, bh0, bh1);
            hmma16816(acc[t][0], acc[t][1], acc[t][2], acc[t][3],
                      ah0, ah1, ah2, ah3, bl0, bl1);
            hmma16816(acc[t][0], acc[t][1], acc[t][2], acc[t][3],
                      al0, al1, al2, al3, bh0, bh1);
        }
    }
}

// ---------------- HMMA transform for levels 8 and 4 (bf16x3) ----------------
template <int LEVEL>
__global__ __launch_bounds__(128) void transform_hmma_kernel()
{
    __shared__ __align__(16) __nv_bfloat16 sh_Ah[64 * A_STRIDE];
    __shared__ __align__(16) __nv_bfloat16 sh_Al[64 * A_STRIDE];
    __shared__ __align__(16) uint32_t sh_Bh[96 * B_U32];
    __shared__ __align__(16) uint32_t sh_Bl[96 * B_U32];

    int tid  = threadIdx.x;
    int wid  = tid >> 5;
    int lane = tid & 31;
    int base = blockIdx.x * 64;

    const float* SUMS = (LEVEL == 4) ? g_sums4 : g_sums8;
    const float* CNT  = (LEVEL == 4) ? g_cnt4  : g_cnt8;
    const int LIDX = (LEVEL == 4) ? 1 : 2;

    stage_W(sh_Bh, sh_Bl, g_Wh32 + LIDX * 3072, g_Wl32 + LIDX * 3072, tid);

    for (int it = tid; it < 1024; it += 128) {
        int slot = it >> 4, kc = it & 15;
        int s = base + slot;
        float inv = 1.0f / fmaxf(CNT[s], 1.0f);
        float4 v = *(const float4*)&SUMS[(long)s * 64 + kc * 4];
        uint32_t h0, l0, h1, l1;
        split2(v.x * inv, v.y * inv, h0, l0);
        split2(v.z * inv, v.w * inv, h1, l1);
        uint32_t* dh = (uint32_t*)&sh_Ah[slot * A_STRIDE + kc * 4];
        uint32_t* dl = (uint32_t*)&sh_Al[slot * A_STRIDE + kc * 4];
        dh[0] = h0; dh[1] = h1;
        dl[0] = l0; dl[1] = l1;
    }
    __syncthreads();

    int warp_m = wid * 16;
    int grp = lane >> 2;
    int qid = lane & 3;

    float acc[12][4];
#pragma unroll
    for (int t = 0; t < 12; t++)
#pragma unroll
        for (int j = 0; j < 4; j++) acc[t][j] = 0.f;

    mma_tile(sh_Ah, sh_Al, sh_Bh, sh_Bl, warp_m, grp, qid, acc);

    // epilogue
    int slot0 = warp_m + grp;
    int slot1 = slot0 + 8;
    int s0 = base + slot0;
    int s1 = base + slot1;

    const float* p0;
    const float* p1;
    float* zout;
    if (LEVEL == 8) {
        p0 = &g_base0[(s0 >> 12) * COUT];
        p1 = &g_base0[(s1 >> 12) * COUT];
        zout = g_Z8;
    } else {
        int bb0 = s0 >> 15, xx0 = (s0 >> 10) & 31, yy0 = (s0 >> 5) & 31, zz0 = s0 & 31;
        int bb1 = s1 >> 15, xx1 = (s1 >> 10) & 31, yy1 = (s1 >> 5) & 31, zz1 = s1 & 31;
        p0 = &g_Z8[(long)((bb0 << 12) | ((xx0 >> 1) << 8) | ((yy0 >> 1) << 4) | (zz0 >> 1)) * COUT];
        p1 = &g_Z8[(long)((bb1 << 12) | ((xx1 >> 1) << 8) | ((yy1 >> 1) << 4) | (zz1 >> 1)) * COUT];
        zout = g_Z4;
    }
    float* d0 = zout + (long)s0 * COUT;
    float* d1 = zout + (long)s1 * COUT;

#pragma unroll
    for (int t = 0; t < 12; t++) {
        int c = t * 8 + qid * 2;
        float2 za = *(const float2*)&p0[c];
        float2 zb = *(const float2*)&p1[c];
        *(float2*)&d0[c] = make_float2(acc[t][0] + za.x, acc[t][1] + za.y);
        *(float2*)&d1[c] = make_float2(acc[t][2] + zb.x, acc[t][3] + zb.y);
    }
}

// ---------------- fused level-2 transform + output (bf16x3 HMMA) ----------------
__global__ __launch_bounds__(128) void fused_mma_kernel(float* __restrict__ out)
{
    __shared__ __align__(16) __nv_bfloat16 sh_Ah[64 * A_STRIDE];
    __shared__ __align__(16) __nv_bfloat16 sh_Al[64 * A_STRIDE];
    __shared__ __align__(16) uint32_t sh_Bh[96 * B_U32];
    __shared__ __align__(16) uint32_t sh_Bl[96 * B_U32];
    __shared__ int   s_s4[64];
    __shared__ int   s_sid[64];
    __shared__ float s_inv[64];

    int tid  = threadIdx.x;
    int wid  = tid >> 5;
    int lane = tid & 31;
    int pbase = blockIdx.x * 64;

    if (tid < 64) {
        int s2 = g_seg2[pbase + tid];
        s_sid[tid] = s2;
        int bb = s2 >> 18, xx = (s2 >> 12) & 63, yy = (s2 >> 6) & 63, zz = s2 & 63;
        s_s4[tid] = (bb << 15) | ((xx >> 1) << 10) | ((yy >> 1) << 5) | (zz >> 1);
        s_inv[tid] = 1.0f / fmaxf(g_cnt2[s2], 1.0f);
    }

    stage_W(sh_Bh, sh_Bl, g_Wh32, g_Wl32, tid);   // level-2 block (LIDX 0)
    __syncthreads();

    // stage A: 64 mean rows -> bf16 hi/lo
    for (int it = tid; it < 1024; it += 128) {
        int slot = it >> 4, kc = it & 15;
        int s = s_sid[slot];
        float inv = s_inv[slot];
        float4 v = *(const float4*)&g_sums2[(long)s * 64 + kc * 4];
        uint32_t h0, l0, h1, l1;
        split2(v.x * inv, v.y * inv, h0, l0);
        split2(v.z * inv, v.w * inv, h1, l1);
        uint32_t* dh = (uint32_t*)&sh_Ah[slot * A_STRIDE + kc * 4];
        uint32_t* dl = (uint32_t*)&sh_Al[slot * A_STRIDE + kc * 4];
        dh[0] = h0; dh[1] = h1;
        dl[0] = l0; dl[1] = l1;
    }
    __syncthreads();

    int warp_m = wid * 16;
    int grp = lane >> 2;
    int qid = lane & 3;

    float acc[12][4];
#pragma unroll
    for (int t = 0; t < 12; t++)
#pragma unroll
        for (int j = 0; j < 4; j++) acc[t][j] = 0.f;

    mma_tile(sh_Ah, sh_Al, sh_Bh, sh_Bl, warp_m, grp, qid, acc);

    // epilogue: out[p] = Z4[s4(p)] + D[p]
    int slot0 = warp_m + grp;
    int slot1 = slot0 + 8;
    const float* z0 = &g_Z4[(long)s_s4[slot0] * COUT];
    const float* z1 = &g_Z4[(long)s_s4[slot1] * COUT];
    float* d0 = out + (long)(pbase + slot0) * COUT;
    float* d1 = out + (long)(pbase + slot1) * COUT;

#pragma unroll
    for (int t = 0; t < 12; t++) {
        int c = t * 8 + qid * 2;
        float2 za = *(const float2*)&z0[c];
        float2 zb = *(const float2*)&z1[c];
        *(float2*)&d0[c] = make_float2(acc[t][0] + za.x, acc[t][1] + za.y);
        *(float2*)&d1[c] = make_float2(acc[t][2] + zb.x, acc[t][3] + zb.y);
    }
}

// ---------------- launcher ----------------
extern "C" void kernel_launch(void* const* d_in, const int* in_sizes, int n_in,
                              void* d_out, int out_size)
{
    const float* feats  = (const float*)d_in[0];
    const int*   coords = (const int*)d_in[1];
    const int*   batch  = (const int*)d_in[2];
    const float* W      = (const float*)d_in[3];
    const float* bias   = (const float*)d_in[4];

    zero_kernel<<<2048, 256>>>();
    split_w_kernel<<<36, 256>>>(W);
    scatter_kernel<<<NPTS / 256, 256>>>((const float4*)feats, coords, batch);
    reduce4_kernel<<<(NSEG4 * 16) / 256, 256>>>();
    reduce8_kernel<<<(NSEG8 * 16) / 256, 256>>>();
    l0_kernel<<<NB, 256>>>(W, bias);
    transform_hmma_kernel<8><<<NSEG8 / 64, 128>>>();
    transform_hmma_kernel<4><<<NSEG4 / 64, 128>>>();
    fused_mma_kernel<<<NPTS / 64, 128>>>((float*)d_out);
}